// round 11
// baseline (speedup 1.0000x reference)
#include <cuda_runtime.h>
#include <cuda_bf16.h>
#include <cstdint>

// Problem constants
#define BB 4
#define SS 2048
#define DD 1024
#define HH 16
#define DK 64
#define M_TOT (BB*SS)   // 8192
#define NELEM ((size_t)M_TOT*DD)   // 8M
#define WELEM ((size_t)DD*DD)      // 1M

// ---------------- device-global scratch (allocation-free) -------------------
// converted inputs (row-major [8192,1024])
__device__ __nv_bfloat16 g_xq_hi[NELEM], g_xq_lo[NELEM];
__device__ __nv_bfloat16 g_xk_hi[NELEM], g_xk_lo[NELEM];
__device__ __nv_bfloat16 g_xv_hi[NELEM], g_xv_lo[NELEM];
// converted weights (row-major [1024,1024])
__device__ __nv_bfloat16 g_wq_hi[WELEM], g_wq_lo[WELEM];
__device__ __nv_bfloat16 g_wk_hi[WELEM], g_wk_lo[WELEM];
__device__ __nv_bfloat16 g_wv_hi[WELEM], g_wv_lo[WELEM];
__device__ __nv_bfloat16 g_wo_hi[WELEM], g_wo_lo[WELEM];
// projected q/k/v (head-split [B,H,S,64])
__device__ __nv_bfloat16 g_q_hi[NELEM], g_q_lo[NELEM];
__device__ __nv_bfloat16 g_k_hi[NELEM], g_k_lo[NELEM];
__device__ __nv_bfloat16 g_v_hi[NELEM], g_v_lo[NELEM];
// attention output ([B,S,D] row-major)
__device__ __nv_bfloat16 g_o_hi[NELEM], g_o_lo[NELEM];

// ---------------------------------------------------------------------------
__device__ __forceinline__ uint32_t smem_to_u32(const void* p) {
    uint32_t a;
    asm("{ .reg .u64 t; cvta.to.shared.u64 t, %1; cvt.u32.u64 %0, t; }"
        : "=r"(a) : "l"(p));
    return a;
}
__device__ __forceinline__ void cpasync16(uint32_t s, const void* g) {
    asm volatile("cp.async.cg.shared.global [%0], [%1], 16;"
                 :: "r"(s), "l"(g) : "memory");
}
__device__ __forceinline__ void cp_commit() {
    asm volatile("cp.async.commit_group;" ::: "memory");
}
template<int N> __device__ __forceinline__ void cp_wait() {
    asm volatile("cp.async.wait_group %0;" :: "n"(N) : "memory");
}
__device__ __forceinline__ void ldm_x4(uint32_t* r, uint32_t addr) {
    asm volatile("ldmatrix.sync.aligned.m8n8.x4.shared.b16 {%0,%1,%2,%3}, [%4];"
                 : "=r"(r[0]), "=r"(r[1]), "=r"(r[2]), "=r"(r[3]) : "r"(addr));
}
__device__ __forceinline__ void ldm_x4_t(uint32_t* r, uint32_t addr) {
    asm volatile("ldmatrix.sync.aligned.m8n8.x4.trans.shared.b16 {%0,%1,%2,%3}, [%4];"
                 : "=r"(r[0]), "=r"(r[1]), "=r"(r[2]), "=r"(r[3]) : "r"(addr));
}
__device__ __forceinline__ void mma16816(float* c, const uint32_t* a, const uint32_t* b) {
    asm volatile(
        "mma.sync.aligned.m16n8k16.row.col.f32.bf16.bf16.f32 "
        "{%0,%1,%2,%3}, {%4,%5,%6,%7}, {%8,%9}, {%0,%1,%2,%3};"
        : "+f"(c[0]), "+f"(c[1]), "+f"(c[2]), "+f"(c[3])
        : "r"(a[0]), "r"(a[1]), "r"(a[2]), "r"(a[3]), "r"(b[0]), "r"(b[1]));
}
__device__ __forceinline__ void split4(float4 v, uint2* hi, uint2* lo) {
    __nv_bfloat162 h01 = __floats2bfloat162_rn(v.x, v.y);
    __nv_bfloat162 h23 = __floats2bfloat162_rn(v.z, v.w);
    float l0 = v.x - __bfloat162float(h01.x);
    float l1 = v.y - __bfloat162float(h01.y);
    float l2 = v.z - __bfloat162float(h23.x);
    float l3 = v.w - __bfloat162float(h23.y);
    __nv_bfloat162 L01 = __floats2bfloat162_rn(l0, l1);
    __nv_bfloat162 L23 = __floats2bfloat162_rn(l2, l3);
    hi->x = *(uint32_t*)&h01; hi->y = *(uint32_t*)&h23;
    lo->x = *(uint32_t*)&L01; lo->y = *(uint32_t*)&L23;
}
__device__ __forceinline__ void split2(float a, float b, uint32_t* hi, uint32_t* lo) {
    __nv_bfloat162 h = __floats2bfloat162_rn(a, b);
    float la = a - __bfloat162float(h.x);
    float lb = b - __bfloat162float(h.y);
    __nv_bfloat162 L = __floats2bfloat162_rn(la, lb);
    *hi = *(uint32_t*)&h;
    *lo = *(uint32_t*)&L;
}

// ---------------------------------------------------------------------------
// One-shot fp32 -> bf16 hi/lo converter
// ---------------------------------------------------------------------------
__global__ __launch_bounds__(256) void convert_split_kernel(
    const float4* __restrict__ in, uint2* __restrict__ hi,
    uint2* __restrict__ lo, int n4)
{
    int i = blockIdx.x * 256 + threadIdx.x;
    if (i < n4) {
        uint2 h, l;
        split4(in[i], &h, &l);
        hi[i] = h;
        lo[i] = l;
    }
}

// ===========================================================================
// GEMM (bf16 hi/lo in):  C = A[M,1024] @ W[1024,1024]^T + bias
// 2-stage cp.async double buffer. CTA 128x128, BK=32, 256 thr, 8 warps 2x4.
//   mode 0: fp32 C row-major [M, DD]
//   mode 1: bf16 hi/lo C in head-split [B,H,S,64], scaled by `scale`
// ===========================================================================
#define GST 80          // bytes per 32-elem bf16 row (64 + 16 pad)
#define GBUF 10240      // 128 rows * 80 B
#define GSTAGE 40960    // 4 buffers
#define GSM_TOTAL 81920 // 2 stages

__global__ __launch_bounds__(256, 2) void gemm_bf(
    const __nv_bfloat16* __restrict__ Ahi, const __nv_bfloat16* __restrict__ Alo,
    const __nv_bfloat16* __restrict__ Whi, const __nv_bfloat16* __restrict__ Wlo,
    const float* __restrict__ bias, float* __restrict__ Cf,
    __nv_bfloat16* __restrict__ Chi, __nv_bfloat16* __restrict__ Clo,
    float scale, int mode)
{
    extern __shared__ char gsm[];
    const uint32_t sbase = smem_to_u32(gsm);

    const int t    = threadIdx.x;
    const int lane = t & 31;
    const int wid  = t >> 5;
    const int bm   = blockIdx.y * 128;
    const int bn   = blockIdx.x * 128;
    const int warpM = wid >> 2;
    const int warpN = wid & 3;

    float acc[4][4][4];
    #pragma unroll
    for (int i = 0; i < 4; i++)
        #pragma unroll
        for (int j = 0; j < 4; j++)
            #pragma unroll
            for (int e = 0; e < 4; e++) acc[i][j][e] = 0.f;

    // cp.async indexing: 512 16B-chunks per buffer, 2 per thread
    const int lrow0 = t >> 2;       // 0..63
    const int lc16  = t & 3;        // 16B column
    #define LOAD_STAGE(kt, stage) do {                                          \
        const int _k0 = (kt) * 32;                                              \
        const uint32_t _so = sbase + (stage) * GSTAGE;                          \
        _Pragma("unroll")                                                       \
        for (int _i = 0; _i < 2; _i++) {                                        \
            const int _r = lrow0 + _i * 64;                                     \
            const uint32_t _sb = (uint32_t)(_r * GST + lc16 * 16);              \
            const size_t _ga = (size_t)(bm + _r) * DD + _k0 + lc16 * 8;         \
            const size_t _gw = (size_t)(bn + _r) * DD + _k0 + lc16 * 8;         \
            cpasync16(_so + 0*GBUF + _sb, Ahi + _ga);                           \
            cpasync16(_so + 1*GBUF + _sb, Alo + _ga);                           \
            cpasync16(_so + 2*GBUF + _sb, Whi + _gw);                           \
            cpasync16(_so + 3*GBUF + _sb, Wlo + _gw);                           \
        }                                                                       \
    } while (0)

    LOAD_STAGE(0, 0); cp_commit();
    LOAD_STAGE(1, 1); cp_commit();
    cp_wait<1>();
    __syncthreads();

    // fragment address components
    const uint32_t aOffBase =
        (uint32_t)((warpM * 64 + (lane & 15)) * GST) + ((lane >> 4) * 16);
    const uint32_t bOffBase =
        (uint32_t)((warpN * 32 + (lane & 7) + ((lane >> 4) << 3)) * GST)
        + (((lane >> 3) & 1) * 16);

    for (int kt = 0; kt < 32; kt++) {
        const uint32_t so = sbase + (kt & 1) * GSTAGE;
        const uint32_t aHiB = so + 0*GBUF, aLoB = so + 1*GBUF;
        const uint32_t bHiB = so + 2*GBUF, bLoB = so + 3*GBUF;

        #pragma unroll
        for (int ks = 0; ks < 2; ks++) {
            const uint32_t ko = (uint32_t)(ks * 32);
            uint32_t bhi[4][2], blo[4][2];
            #pragma unroll
            for (int pair = 0; pair < 2; pair++) {
                uint32_t off = bOffBase + (uint32_t)(pair * 16 * GST) + ko;
                uint32_t r4[4];
                ldm_x4(r4, bHiB + off);
                bhi[2*pair+0][0] = r4[0]; bhi[2*pair+0][1] = r4[1];
                bhi[2*pair+1][0] = r4[2]; bhi[2*pair+1][1] = r4[3];
                ldm_x4(r4, bLoB + off);
                blo[2*pair+0][0] = r4[0]; blo[2*pair+0][1] = r4[1];
                blo[2*pair+1][0] = r4[2]; blo[2*pair+1][1] = r4[3];
            }
            #pragma unroll
            for (int mt = 0; mt < 4; mt++) {
                uint32_t off = aOffBase + (uint32_t)(mt * 16 * GST) + ko;
                uint32_t ahi[4], alo[4];
                ldm_x4(ahi, aHiB + off);
                ldm_x4(alo, aLoB + off);
                #pragma unroll
                for (int nt = 0; nt < 4; nt++) {
                    mma16816(acc[mt][nt], ahi, bhi[nt]);
                    mma16816(acc[mt][nt], ahi, blo[nt]);
                    mma16816(acc[mt][nt], alo, bhi[nt]);
                }
            }
        }

        __syncthreads();
        if (kt + 2 < 32) {
            LOAD_STAGE(kt + 2, kt & 1);
            cp_commit();
            cp_wait<1>();
        } else {
            cp_wait<0>();
        }
        __syncthreads();
    }

    // epilogue
    const int groupID = lane >> 2;
    const int laneCol = (lane & 3) * 2;
    #pragma unroll
    for (int mt = 0; mt < 4; mt++) {
        #pragma unroll
        for (int nt = 0; nt < 4; nt++) {
            const int n = bn + warpN * 32 + nt * 8 + laneCol;
            const float2 bv = *(const float2*)(bias + n);
            #pragma unroll
            for (int hh = 0; hh < 2; hh++) {
                const int m = bm + warpM * 64 + mt * 16 + groupID + hh * 8;
                float ox = acc[mt][nt][2*hh+0] + bv.x;
                float oy = acc[mt][nt][2*hh+1] + bv.y;
                if (mode == 0) {
                    *(float2*)(Cf + (size_t)m * DD + n) = make_float2(ox, oy);
                } else {
                    ox *= scale; oy *= scale;
                    uint32_t h32, l32;
                    split2(ox, oy, &h32, &l32);
                    const int b_ = m >> 11, s_ = m & 2047;
                    const int h_ = n >> 6,  d_ = n & 63;
                    const size_t idx = ((((size_t)b_ * HH + h_) * SS + s_) << 6) + d_;
                    *(uint32_t*)(Chi + idx) = h32;
                    *(uint32_t*)(Clo + idx) = l32;
                }
            }
        }
    }
}

// ===========================================================================
// Tensor-core flash attention (bf16 hi/lo in, cp.async staging).
// CTA: one (b,h), 128 q-rows, 4 warps x 32 rows. KV tile = 64 keys.
// ===========================================================================
#define FST 144
#define FQHI 0
#define FQLO 18432
#define FKHI 36864
#define FKLO 46080
#define FVHI 55296
#define FVLO 64512
#define FSM_TOTAL 73728

__global__ __launch_bounds__(128, 2) void flash_mma()
{
    extern __shared__ char fsm[];
    const uint32_t fbase = smem_to_u32(fsm);
    const int t    = threadIdx.x;
    const int lane = t & 31;
    const int warp = t >> 5;
    const int qb = blockIdx.x, h = blockIdx.y, b = blockIdx.z;

    const size_t head_base = ((size_t)b * HH + h) * SS * DK;
    const __nv_bfloat16* qhiH = g_q_hi + head_base;
    const __nv_bfloat16* qloH = g_q_lo + head_base;
    const __nv_bfloat16* khiH = g_k_hi + head_base;
    const __nv_bfloat16* kloH = g_k_lo + head_base;
    const __nv_bfloat16* vhiH = g_v_hi + head_base;
    const __nv_bfloat16* vloH = g_v_lo + head_base;

    // --- stage Q (once) + KV tile 0 ---
    #pragma unroll
    for (int i = 0; i < 8; i++) {
        const int chunk = t + i * 128;       // 0..1023
        const int r = chunk >> 3, c16 = chunk & 7;
        const uint32_t sb = (uint32_t)(r * FST + c16 * 16);
        const size_t ga = (size_t)(qb * 128 + r) * 64 + c16 * 8;
        cpasync16(fbase + FQHI + sb, qhiH + ga);
        cpasync16(fbase + FQLO + sb, qloH + ga);
    }
    #pragma unroll
    for (int i = 0; i < 4; i++) {
        const int chunk = t + i * 128;       // 0..511
        const int r = chunk >> 3, c16 = chunk & 7;
        const uint32_t sb = (uint32_t)(r * FST + c16 * 16);
        const size_t ga = (size_t)r * 64 + c16 * 8;
        cpasync16(fbase + FKHI + sb, khiH + ga);
        cpasync16(fbase + FKLO + sb, kloH + ga);
        cpasync16(fbase + FVHI + sb, vhiH + ga);
        cpasync16(fbase + FVLO + sb, vloH + ga);
    }
    cp_commit();
    cp_wait<0>();
    __syncthreads();

    float o[2][8][4];
    #pragma unroll
    for (int mt = 0; mt < 2; mt++)
        #pragma unroll
        for (int nv = 0; nv < 8; nv++)
            #pragma unroll
            for (int e = 0; e < 4; e++) o[mt][nv][e] = 0.f;
    float mrow[2][2] = {{-1e30f, -1e30f}, {-1e30f, -1e30f}};
    float lrow[2][2] = {{0.f, 0.f}, {0.f, 0.f}};

    const uint32_t aRow  = (uint32_t)(warp * 32 + (lane & 15));
    const uint32_t aCol  = (uint32_t)((lane >> 4) << 4);
    const uint32_t kRow  = (uint32_t)((lane & 7) + ((lane >> 4) << 3));
    const uint32_t kCol  = (uint32_t)(((lane >> 3) & 1) << 4);
    const uint32_t vRow  = (uint32_t)(lane & 15);
    const uint32_t vCol  = (uint32_t)((lane >> 4) << 4);

    for (int kb = 0; kb < SS / 64; kb++) {
        // ---- QK^T ----
        float s[2][8][4];
        #pragma unroll
        for (int mt = 0; mt < 2; mt++)
            #pragma unroll
            for (int nt = 0; nt < 8; nt++)
                #pragma unroll
                for (int e = 0; e < 4; e++) s[mt][nt][e] = 0.f;

        #pragma unroll
        for (int ks = 0; ks < 4; ks++) {
            const uint32_t ko = (uint32_t)(ks * 32);
            uint32_t bhi[8][2], blo[8][2];
            #pragma unroll
            for (int pp = 0; pp < 4; pp++) {
                uint32_t off = (kRow + pp * 16) * FST + kCol + ko;
                uint32_t r4[4];
                ldm_x4(r4, fbase + FKHI + off);
                bhi[2*pp+0][0] = r4[0]; bhi[2*pp+0][1] = r4[1];
                bhi[2*pp+1][0] = r4[2]; bhi[2*pp+1][1] = r4[3];
                ldm_x4(r4, fbase + FKLO + off);
                blo[2*pp+0][0] = r4[0]; blo[2*pp+0][1] = r4[1];
                blo[2*pp+1][0] = r4[2]; blo[2*pp+1][1] = r4[3];
            }
            #pragma unroll
            for (int mt = 0; mt < 2; mt++) {
                uint32_t off = (aRow + mt * 16) * FST + aCol + ko;
                uint32_t ahi[4], alo[4];
                ldm_x4(ahi, fbase + FQHI + off);
                ldm_x4(alo, fbase + FQLO + off);
                #pragma unroll
                for (int nt = 0; nt < 8; nt++) {
                    mma16816(s[mt][nt], ahi, bhi[nt]);
                    mma16816(s[mt][nt], ahi, blo[nt]);
                    mma16816(s[mt][nt], alo, bhi[nt]);
                }
            }
        }

        // ---- online softmax ----
        #pragma unroll
        for (int mt = 0; mt < 2; mt++) {
            float mx0 = -1e30f, mx1 = -1e30f;
            #pragma unroll
            for (int nt = 0; nt < 8; nt++) {
                mx0 = fmaxf(mx0, fmaxf(s[mt][nt][0], s[mt][nt][1]));
                mx1 = fmaxf(mx1, fmaxf(s[mt][nt][2], s[mt][nt][3]));
            }
            mx0 = fmaxf(mx0, __shfl_xor_sync(0xffffffffu, mx0, 1));
            mx0 = fmaxf(mx0, __shfl_xor_sync(0xffffffffu, mx0, 2));
            mx1 = fmaxf(mx1, __shfl_xor_sync(0xffffffffu, mx1, 1));
            mx1 = fmaxf(mx1, __shfl_xor_sync(0xffffffffu, mx1, 2));

            const float mn0 = fmaxf(mrow[mt][0], mx0);
            const float mn1 = fmaxf(mrow[mt][1], mx1);
            const float c0 = __expf(mrow[mt][0] - mn0);
            const float c1 = __expf(mrow[mt][1] - mn1);
            mrow[mt][0] = mn0; mrow[mt][1] = mn1;

            float sum0 = 0.f, sum1 = 0.f;
            #pragma unroll
            for (int nt = 0; nt < 8; nt++) {
                float p0 = __expf(s[mt][nt][0] - mn0);
                float p1 = __expf(s[mt][nt][1] - mn0);
                float p2 = __expf(s[mt][nt][2] - mn1);
                float p3 = __expf(s[mt][nt][3] - mn1);
                s[mt][nt][0] = p0; s[mt][nt][1] = p1;
                s[mt][nt][2] = p2; s[mt][nt][3] = p3;
                sum0 += p0 + p1; sum1 += p2 + p3;
            }
            sum0 += __shfl_xor_sync(0xffffffffu, sum0, 1);
            sum0 += __shfl_xor_sync(0xffffffffu, sum0, 2);
            sum1 += __shfl_xor_sync(0xffffffffu, sum1, 1);
            sum1 += __shfl_xor_sync(0xffffffffu, sum1, 2);
            lrow[mt][0] = lrow[mt][0] * c0 + sum0;
            lrow[mt][1] = lrow[mt][1] * c1 + sum1;

            #pragma unroll
            for (int nv = 0; nv < 8; nv++) {
                o[mt][nv][0] *= c0; o[mt][nv][1] *= c0;
                o[mt][nv][2] *= c1; o[mt][nv][3] *= c1;
            }
        }

        // ---- PV ----
        #pragma unroll
        for (int ks = 0; ks < 4; ks++) {
            uint32_t vhi[8][2], vlo[8][2];
            #pragma unroll
            for (int pv = 0; pv < 4; pv++) {
                uint32_t off = (vRow + ks * 16) * FST + pv * 32 + vCol;
                uint32_t r4[4];
                ldm_x4_t(r4, fbase + FVHI + off);
                vhi[2*pv+0][0] = r4[0]; vhi[2*pv+0][1] = r4[1];
                vhi[2*pv+1][0] = r4[2]; vhi[2*pv+1][1] = r4[3];
                ldm_x4_t(r4, fbase + FVLO + off);
                vlo[2*pv+0][0] = r4[0]; vlo[2*pv+0][1] = r4[1];
                vlo[2*pv+1][0] = r4[2]; vlo[2*pv+1][1] = r4[3];
            }
            #pragma unroll
            for (int mt = 0; mt < 2; mt++) {
                uint32_t phi[4], plo[4];
                split2(s[mt][2*ks+0][0], s[mt][2*ks+0][1], &phi[0], &plo[0]);
                split2(s[mt][2*ks+0][2], s[mt][2*ks+0][3], &phi[1], &plo[1]);
                split2(s[mt][2*ks+1][0], s[mt][2*ks+1][1], &phi[2], &plo[2]);
                split2(s[mt][2*ks+1][2], s[mt][2*ks+1][3], &phi[3], &plo[3]);
                #pragma unroll
                for (int nv = 0; nv < 8; nv++) {
                    mma16816(o[mt][nv], phi, vhi[nv]);
                    mma16816(o[mt][nv], phi, vlo[nv]);
                    mma16816(o[mt][nv], plo, vhi[nv]);
                }
            }
        }

        // ---- stage next KV tile ----
        if (kb + 1 < SS / 64) {
            __syncthreads();
            #pragma unroll
            for (int i = 0; i < 4; i++) {
                const int chunk = t + i * 128;
                const int r = chunk >> 3, c16 = chunk & 7;
                const uint32_t sb = (uint32_t)(r * FST + c16 * 16);
                const size_t ga = (size_t)((kb + 1) * 64 + r) * 64 + c16 * 8;
                cpasync16(fbase + FKHI + sb, khiH + ga);
                cpasync16(fbase + FKLO + sb, kloH + ga);
                cpasync16(fbase + FVHI + sb, vhiH + ga);
                cpasync16(fbase + FVLO + sb, vloH + ga);
            }
            cp_commit();
            cp_wait<0>();
            __syncthreads();
        }
    }

    // ---- epilogue: normalize, split, write [B,S,D] hi/lo bf16 ----
    const int groupID = lane >> 2;
    const int laneCol = (lane & 3) * 2;
    #pragma unroll
    for (int mt = 0; mt < 2; mt++) {
        const float inv0 = 1.f / lrow[mt][0];
        const float inv1 = 1.f / lrow[mt][1];
        const int r0 = qb * 128 + warp * 32 + mt * 16 + groupID;
        #pragma unroll
        for (int nv = 0; nv < 8; nv++) {
            const int col = h * 64 + nv * 8 + laneCol;
            uint32_t h32, l32;
            split2(o[mt][nv][0] * inv0, o[mt][nv][1] * inv0, &h32, &l32);
            const size_t i0 = (size_t)(b * SS + r0) * DD + col;
            *(uint32_t*)(g_o_hi + i0) = h32;
            *(uint32_t*)(g_o_lo + i0) = l32;
            split2(o[mt][nv][2] * inv1, o[mt][nv][3] * inv1, &h32, &l32);
            const size_t i1 = (size_t)(b * SS + r0 + 8) * DD + col;
            *(uint32_t*)(g_o_hi + i1) = h32;
            *(uint32_t*)(g_o_lo + i1) = l32;
        }
    }
}

// ---------------------------------------------------------------------------
extern "C" void kernel_launch(void* const* d_in, const int* in_sizes, int n_in,
                              void* d_out, int out_size)
{
    const float* query = (const float*)d_in[0];
    const float* key   = (const float*)d_in[1];
    const float* value = (const float*)d_in[2];
    const float* Wq    = (const float*)d_in[3];
    const float* bq    = (const float*)d_in[4];
    const float* Wk    = (const float*)d_in[5];
    const float* bk    = (const float*)d_in[6];
    const float* Wv    = (const float*)d_in[7];
    const float* bv    = (const float*)d_in[8];
    const float* Wo    = (const float*)d_in[9];
    const float* bo    = (const float*)d_in[10];
    float* out = (float*)d_out;

    #define SYM(p, s) void* p; cudaGetSymbolAddress(&p, s)
    SYM(xq_hi, g_xq_hi); SYM(xq_lo, g_xq_lo);
    SYM(xk_hi, g_xk_hi); SYM(xk_lo, g_xk_lo);
    SYM(xv_hi, g_xv_hi); SYM(xv_lo, g_xv_lo);
    SYM(wq_hi, g_wq_hi); SYM(wq_lo, g_wq_lo);
    SYM(wk_hi, g_wk_hi); SYM(wk_lo, g_wk_lo);
    SYM(wv_hi, g_wv_hi); SYM(wv_lo, g_wv_lo);
    SYM(wo_hi, g_wo_hi); SYM(wo_lo, g_wo_lo);
    SYM(q_hi,  g_q_hi);  SYM(q_lo,  g_q_lo);
    SYM(k_hi,  g_k_hi);  SYM(k_lo,  g_k_lo);
    SYM(v_hi,  g_v_hi);  SYM(v_lo,  g_v_lo);
    SYM(o_hi,  g_o_hi);  SYM(o_lo,  g_o_lo);
    #undef SYM

    cudaFuncSetAttribute(gemm_bf,  cudaFuncAttributeMaxDynamicSharedMemorySize, GSM_TOTAL);
    cudaFuncSetAttribute(flash_mma, cudaFuncAttributeMaxDynamicSharedMemorySize, FSM_TOTAL);

    const int n4_in = (int)(NELEM / 4);   // 2M
    const int n4_w  = (int)(WELEM / 4);   // 256K
    convert_split_kernel<<<(n4_in + 255) / 256, 256>>>(
        (const float4*)query, (uint2*)xq_hi, (uint2*)xq_lo, n4_in);
    convert_split_kernel<<<(n4_in + 255) / 256, 256>>>(
        (const float4*)key,   (uint2*)xk_hi, (uint2*)xk_lo, n4_in);
    convert_split_kernel<<<(n4_in + 255) / 256, 256>>>(
        (const float4*)value, (uint2*)xv_hi, (uint2*)xv_lo, n4_in);
    convert_split_kernel<<<(n4_w + 255) / 256, 256>>>(
        (const float4*)Wq, (uint2*)wq_hi, (uint2*)wq_lo, n4_w);
    convert_split_kernel<<<(n4_w + 255) / 256, 256>>>(
        (const float4*)Wk, (uint2*)wk_hi, (uint2*)wk_lo, n4_w);
    convert_split_kernel<<<(n4_w + 255) / 256, 256>>>(
        (const float4*)Wv, (uint2*)wv_hi, (uint2*)wv_lo, n4_w);
    convert_split_kernel<<<(n4_w + 255) / 256, 256>>>(
        (const float4*)Wo, (uint2*)wo_hi, (uint2*)wo_lo, n4_w);

    dim3 gemm_grid(DD / 128, M_TOT / 128);   // (8, 64)

    gemm_bf<<<gemm_grid, 256, GSM_TOTAL>>>(
        (const __nv_bfloat16*)xq_hi, (const __nv_bfloat16*)xq_lo,
        (const __nv_bfloat16*)wq_hi, (const __nv_bfloat16*)wq_lo,
        bq, nullptr, (__nv_bfloat16*)q_hi, (__nv_bfloat16*)q_lo, 0.125f, 1);
    gemm_bf<<<gemm_grid, 256, GSM_TOTAL>>>(
        (const __nv_bfloat16*)xk_hi, (const __nv_bfloat16*)xk_lo,
        (const __nv_bfloat16*)wk_hi, (const __nv_bfloat16*)wk_lo,
        bk, nullptr, (__nv_bfloat16*)k_hi, (__nv_bfloat16*)k_lo, 1.0f, 1);
    gemm_bf<<<gemm_grid, 256, GSM_TOTAL>>>(
        (const __nv_bfloat16*)xv_hi, (const __nv_bfloat16*)xv_lo,
        (const __nv_bfloat16*)wv_hi, (const __nv_bfloat16*)wv_lo,
        bv, nullptr, (__nv_bfloat16*)v_hi, (__nv_bfloat16*)v_lo, 1.0f, 1);

    flash_mma<<<dim3(SS / 128, HH, BB), 128, FSM_TOTAL>>>();

    gemm_bf<<<gemm_grid, 256, GSM_TOTAL>>>(
        (const __nv_bfloat16*)o_hi, (const __nv_bfloat16*)o_lo,
        (const __nv_bfloat16*)wo_hi, (const __nv_bfloat16*)wo_lo,
        bo, out, nullptr, nullptr, 1.0f, 0);
}